// round 9
// baseline (speedup 1.0000x reference)
#include <cuda_runtime.h>
#include <cuda_bf16.h>
#include <cstdint>

// ---------------------------------------------------------------------------
// Problem constants
// ---------------------------------------------------------------------------
#define B_   4
#define T_   4096
#define D_   1024
#define E_   1024
#define TWOE 2048
#define BT   (B_ * T_)          // 16384 rows
#define EPS_ 1e-8f

// ---------------------------------------------------------------------------
// Scratch (__device__ globals; no runtime allocation allowed)
// ---------------------------------------------------------------------------
__device__ float         g_z1[(size_t)BT * TWOE];     // in_proj pre-norm (fp32)
__device__ float         g_ssq[BT];                   // row sum-of-squares
__device__ float         g_s1[BT];                    // row rsqrt scale
__device__ __nv_bfloat16 g_uhi[(size_t)BT * D_];
__device__ __nv_bfloat16 g_ulo[(size_t)BT * D_];
__device__ __nv_bfloat16 g_w1hi[(size_t)TWOE * D_];
__device__ __nv_bfloat16 g_w1lo[(size_t)TWOE * D_];
__device__ __nv_bfloat16 g_ghi[(size_t)BT * E_];
__device__ __nv_bfloat16 g_glo[(size_t)BT * E_];
__device__ __nv_bfloat16 g_w2hi[(size_t)D_ * E_];
__device__ __nv_bfloat16 g_w2lo[(size_t)D_ * E_];

// ---------------------------------------------------------------------------
// HMMA split-bf16 GEMM (NT): C[m,n] = sum_k A[m,k]*B[n,k] + bias[n]
//   C = Ahi*Bhi + Alo*Bhi + Ahi*Blo   (fp32 accum; lo*lo dropped)
// 256x128 CTA tile, 512 threads, 16 warps -> warp tile 64x32, m16n8k16.
// GK=32 (two k16 steps per barrier), 3-stage cp.async circular pipeline
// (wait_group 1, one barrier per chunk), 144KB dynamic smem, 1 CTA/SM
// (16 warps = RF-capped maximum either way).
// Swizzle (64B rows): row r, 16B chunk c -> r*64 + ((c ^ ((r>>1)&3)) * 16).
// Optional: epilogue atomically accumulates per-row sum(C^2) into ssq.
// ---------------------------------------------------------------------------
#define GM 256
#define GN 128
#define GK 32
#define NTHR 512
#define ROWB 64                      // bytes per smem row (32 bf16)
#define ATILEB (256 * ROWB)          // 16384 B per A tile
#define BTILEB (128 * ROWB)          // 8192 B per B tile
#define STAGEB (2 * ATILEB + 2 * BTILEB)   // 49152 B (Ahi, Alo, Bhi, Blo)
#define STAGES 3
#define GEMM_SMEM (STAGES * STAGEB)  // 147456 B

#define OFF_AHI 0
#define OFF_ALO (ATILEB)
#define OFF_BHI (2 * ATILEB)
#define OFF_BLO (2 * ATILEB + BTILEB)

__device__ __forceinline__ uint32_t smem_u32(const void* p) {
    uint32_t a;
    asm("{ .reg .u64 t; cvta.to.shared.u64 t, %1; cvt.u32.u64 %0, t; }" : "=r"(a) : "l"(p));
    return a;
}
__device__ __forceinline__ void cp_async16(uint32_t dst, const void* src) {
    asm volatile("cp.async.cg.shared.global [%0], [%1], 16;\n" :: "r"(dst), "l"(src));
}
__device__ __forceinline__ void cp_commit() { asm volatile("cp.async.commit_group;\n"); }
template <int N>
__device__ __forceinline__ void cp_wait() { asm volatile("cp.async.wait_group %0;\n" :: "n"(N)); }

__device__ __forceinline__ void ldmat_x4(uint32_t* r, uint32_t addr) {
    asm volatile("ldmatrix.sync.aligned.m8n8.x4.shared.b16 {%0,%1,%2,%3}, [%4];"
                 : "=r"(r[0]), "=r"(r[1]), "=r"(r[2]), "=r"(r[3]) : "r"(addr));
}
__device__ __forceinline__ void mma_bf16(float* d, const uint32_t* a, const uint32_t* b) {
    asm volatile(
        "mma.sync.aligned.m16n8k16.row.col.f32.bf16.bf16.f32 "
        "{%0,%1,%2,%3}, {%4,%5,%6,%7}, {%8,%9}, {%0,%1,%2,%3};"
        : "+f"(d[0]), "+f"(d[1]), "+f"(d[2]), "+f"(d[3])
        : "r"(a[0]), "r"(a[1]), "r"(a[2]), "r"(a[3]), "r"(b[0]), "r"(b[1]));
}

// swizzled byte offset for (row, 16B-chunk 0..3) in a 64B-row tile
__device__ __forceinline__ uint32_t swz(int row, int c16) {
    return (uint32_t)(row * ROWB + ((c16 ^ ((row >> 1) & 3)) * 16));
}

__global__ __launch_bounds__(NTHR, 1)
void gemm_hmma_bf16x2(const __nv_bfloat16* __restrict__ Ahi, const __nv_bfloat16* __restrict__ Alo,
                      const __nv_bfloat16* __restrict__ Bhi, const __nv_bfloat16* __restrict__ Blo,
                      const float* __restrict__ bias, float* __restrict__ C,
                      int M, int N, int K, float* __restrict__ ssq)
{
    extern __shared__ char smem[];
    const uint32_t sbase = smem_u32(smem);
    const int tid  = threadIdx.x;
    const int wid  = tid >> 5;                 // 0..15
    const int lane = tid & 31;
    const int bm = blockIdx.y * GM;
    const int bn = blockIdx.x * GN;
    const int wm = (wid >> 2) * 64;            // 0/64/128/192
    const int wn = (wid & 3) * 32;             // 0/32/64/96

    // stage loader: A tiles 2x(256x4 chunks)=2048, B tiles 2x(128x4)=1024
    // total 3072 cp.async / 512 thr = 6 per thread
    auto load_stage = [&](int stage, int k0) {
        const uint32_t dst0 = sbase + stage * STAGEB;
        #pragma unroll
        for (int i = 0; i < 6; ++i) {
            int id = tid + i * NTHR;           // 0..3071
            if (id < 2048) {                   // A tiles
                int t   = id >> 10;            // 0 = hi, 1 = lo
                int w   = id & 1023;
                int row = w >> 2;
                int c   = w & 3;
                const __nv_bfloat16* src =
                    (t ? Alo : Ahi) + (size_t)(bm + row) * K + k0 + c * 8;
                cp_async16(dst0 + (t ? OFF_ALO : OFF_AHI) + swz(row, c), src);
            } else {                           // B tiles
                int id2 = id - 2048;
                int t   = id2 >> 9;            // 0 = hi, 1 = lo
                int w   = id2 & 511;
                int row = w >> 2;
                int c   = w & 3;
                const __nv_bfloat16* src =
                    (t ? Blo : Bhi) + (size_t)(bn + row) * K + k0 + c * 8;
                cp_async16(dst0 + (t ? OFF_BLO : OFF_BHI) + swz(row, c), src);
            }
        }
        cp_commit();
    };

    float acc[4][4][4];
    #pragma unroll
    for (int i = 0; i < 4; ++i)
        #pragma unroll
        for (int j = 0; j < 4; ++j)
            #pragma unroll
            for (int q = 0; q < 4; ++q) acc[i][j][q] = 0.f;

    const int chunks = K / GK;
    load_stage(0, 0);
    load_stage(1, GK);

    // lane->tile-offset decode for ldmatrix (fixed per lane)
    const int l8  = lane & 7;
    const int sel = lane >> 3;                 // 0..3
    const int a_row = (sel & 1) * 8 + l8;
    const int a_c   = sel >> 1;                // 8-col half within a k16 step
    const int b_row = (sel >> 1) * 8 + l8;
    const int b_c   = sel & 1;

    uint32_t ra[2][4], rb[2][2];
    #pragma unroll
    for (int s = 0; s < 2; ++s) {
        #pragma unroll
        for (int mi = 0; mi < 4; ++mi)
            ra[s][mi] = swz(wm + mi * 16 + a_row, 2 * s + a_c);
        #pragma unroll
        for (int jp = 0; jp < 2; ++jp)
            rb[s][jp] = swz(wn + jp * 16 + b_row, 2 * s + b_c);
    }

    int stage = 0;
    for (int ch = 0; ch < chunks; ++ch) {
        cp_wait<1>();                           // current stage landed
        __syncthreads();                        // visible; oldest buffer consumed
        if (ch + 2 < chunks) {
            int ns = stage + 2; if (ns >= STAGES) ns -= STAGES;
            load_stage(ns, (ch + 2) * GK);
        }

        const uint32_t st = sbase + stage * STAGEB;
        const uint32_t aHiB = st + OFF_AHI;
        const uint32_t aLoB = st + OFF_ALO;
        const uint32_t bHiB = st + OFF_BHI;
        const uint32_t bLoB = st + OFF_BLO;

        #pragma unroll
        for (int s = 0; s < 2; ++s) {           // two k16 steps, no barrier between
            uint32_t ahi[4][4], alo[4][4], bfr[4][2];
            #pragma unroll
            for (int mi = 0; mi < 4; ++mi) {
                ldmat_x4(ahi[mi], aHiB + ra[s][mi]);
                ldmat_x4(alo[mi], aLoB + ra[s][mi]);
            }
            #pragma unroll
            for (int jp = 0; jp < 2; ++jp) {
                uint32_t th[4];
                ldmat_x4(th, bHiB + rb[s][jp]);
                bfr[jp*2  ][0] = th[0]; bfr[jp*2  ][1] = th[1];
                bfr[jp*2+1][0] = th[2]; bfr[jp*2+1][1] = th[3];
            }
            #pragma unroll
            for (int mi = 0; mi < 4; ++mi)
                #pragma unroll
                for (int nj = 0; nj < 4; ++nj) {
                    mma_bf16(acc[mi][nj], ahi[mi], bfr[nj]);
                    mma_bf16(acc[mi][nj], alo[mi], bfr[nj]);
                }
            #pragma unroll
            for (int jp = 0; jp < 2; ++jp) {
                uint32_t tl[4];
                ldmat_x4(tl, bLoB + rb[s][jp]);
                bfr[jp*2  ][0] = tl[0]; bfr[jp*2  ][1] = tl[1];
                bfr[jp*2+1][0] = tl[2]; bfr[jp*2+1][1] = tl[3];
            }
            #pragma unroll
            for (int mi = 0; mi < 4; ++mi)
                #pragma unroll
                for (int nj = 0; nj < 4; ++nj)
                    mma_bf16(acc[mi][nj], ahi[mi], bfr[nj]);
        }

        ++stage; if (stage >= STAGES) stage = 0;
    }

    // epilogue: frag layout row = lane/4 (+8), col = 2*(lane%4) (+1)
    const int er = lane >> 2;
    const int ec = (lane & 3) * 2;
    #pragma unroll
    for (int mi = 0; mi < 4; ++mi) {
        float pr0 = 0.f, pr1 = 0.f;
        #pragma unroll
        for (int nj = 0; nj < 4; ++nj) {
            int row0 = bm + wm + mi * 16 + er;
            int col  = bn + wn + nj * 8 + ec;
            float b0 = bias[col], b1 = bias[col + 1];
            float v00 = acc[mi][nj][0] + b0, v01 = acc[mi][nj][1] + b1;
            float v10 = acc[mi][nj][2] + b0, v11 = acc[mi][nj][3] + b1;
            *(float2*)&C[(size_t)row0 * N + col]       = make_float2(v00, v01);
            *(float2*)&C[(size_t)(row0 + 8) * N + col] = make_float2(v10, v11);
            pr0 += v00 * v00 + v01 * v01;
            pr1 += v10 * v10 + v11 * v11;
        }
        if (ssq) {
            int row0 = bm + wm + mi * 16 + er;
            #pragma unroll
            for (int o = 1; o < 4; o <<= 1) {
                pr0 += __shfl_xor_sync(0xffffffff, pr0, o);
                pr1 += __shfl_xor_sync(0xffffffff, pr1, o);
            }
            if ((lane & 3) == 0) {
                atomicAdd(&ssq[row0],     pr0);
                atomicAdd(&ssq[row0 + 8], pr1);
            }
        }
    }
}

// ---------------------------------------------------------------------------
// Elementwise kernels
// ---------------------------------------------------------------------------
__global__ void zero_f32(float* __restrict__ p, int n)
{
    int i = blockIdx.x * blockDim.x + threadIdx.x;
    if (i < n) p[i] = 0.f;
}

__global__ void split_bf16(const float* __restrict__ x,
                           __nv_bfloat16* __restrict__ hi, __nv_bfloat16* __restrict__ lo,
                           int n4)
{
    int i = blockIdx.x * blockDim.x + threadIdx.x;
    if (i >= n4) return;
    float4 v = ((const float4*)x)[i];
    __nv_bfloat16 h[4], l[4];
    float f[4] = {v.x, v.y, v.z, v.w};
    #pragma unroll
    for (int j = 0; j < 4; ++j) {
        h[j] = __float2bfloat16(f[j]);
        l[j] = __float2bfloat16(f[j] - __bfloat162float(h[j]));
    }
    ((uint2*)hi)[i] = *(uint2*)h;
    ((uint2*)lo)[i] = *(uint2*)l;
}

__global__ void s1_from_ssq(const float* __restrict__ ssq, float* __restrict__ s, int n)
{
    int i = blockIdx.x * blockDim.x + threadIdx.x;
    if (i < n) s[i] = rsqrtf(ssq[i] * (1.0f / TWOE) + EPS_);
}

__global__ void conv_gate(const float* __restrict__ z1, const float* __restrict__ s1,
                          const float* __restrict__ innw,
                          const float* __restrict__ cw, const float* __restrict__ cb,
                          __nv_bfloat16* __restrict__ ghi, __nv_bfloat16* __restrict__ glo)
{
    const int idx = blockIdx.x * blockDim.x + threadIdx.x;   // over BT*E
    const int e   = idx & (E_ - 1);
    const int row = idx >> 10;
    const int t   = row & (T_ - 1);

    const float wn  = innw[e];
    const float wnv = innw[E_ + e];
    const float w0 = cw[e * 3 + 0], w1 = cw[e * 3 + 1], w2 = cw[e * 3 + 2];

    const float sc = s1[row];
    float xm = cb[e];
    if (t > 0)
        xm = fmaf(w0, z1[(size_t)(row - 1) * TWOE + e] * s1[row - 1] * wn, xm);
    xm = fmaf(w1, z1[(size_t)row * TWOE + e] * sc * wn, xm);
    if (t < T_ - 1)
        xm = fmaf(w2, z1[(size_t)(row + 1) * TWOE + e] * s1[row + 1] * wn, xm);
    const float v = z1[(size_t)row * TWOE + E_ + e] * sc * wnv;
    const float g = v * xm;
    __nv_bfloat16 h = __float2bfloat16(g);
    ghi[idx] = h;
    glo[idx] = __float2bfloat16(g - __bfloat162float(h));
}

__global__ void out_rmsnorm(float* __restrict__ out, const float* __restrict__ w)
{
    const int row = blockIdx.x;
    float4* p = (float4*)(out + (size_t)row * D_);
    float4 v = p[threadIdx.x];                  // 256 x 4 = 1024
    float acc = v.x*v.x + v.y*v.y + v.z*v.z + v.w*v.w;
    #pragma unroll
    for (int o = 16; o > 0; o >>= 1) acc += __shfl_xor_sync(0xffffffff, acc, o);
    __shared__ float warpsum[8];
    __shared__ float s_bcast;
    if ((threadIdx.x & 31) == 0) warpsum[threadIdx.x >> 5] = acc;
    __syncthreads();
    if (threadIdx.x == 0) {
        float tsum = 0.f;
        #pragma unroll
        for (int wi = 0; wi < 8; ++wi) tsum += warpsum[wi];
        s_bcast = rsqrtf(tsum * (1.0f / D_) + EPS_);
    }
    __syncthreads();
    const float s = s_bcast;
    float4 wv = *(const float4*)&w[threadIdx.x * 4];
    v.x *= s * wv.x; v.y *= s * wv.y; v.z *= s * wv.z; v.w *= s * wv.w;
    p[threadIdx.x] = v;
}

// ---------------------------------------------------------------------------
// Launch
// Inputs (metadata order): u, W_in, b_in, in_norm_w, conv_w, conv_b,
//                          W_out, b_out, out_norm_w
// ---------------------------------------------------------------------------
extern "C" void kernel_launch(void* const* d_in, const int* in_sizes, int n_in,
                              void* d_out, int out_size)
{
    const float* u      = (const float*)d_in[0];
    const float* W_in   = (const float*)d_in[1];
    const float* b_in   = (const float*)d_in[2];
    const float* innw   = (const float*)d_in[3];
    const float* conv_w = (const float*)d_in[4];
    const float* conv_b = (const float*)d_in[5];
    const float* W_out  = (const float*)d_in[6];
    const float* b_out  = (const float*)d_in[7];
    const float* outnw  = (const float*)d_in[8];
    float* out = (float*)d_out;

    float *z1, *ssq, *s1;
    __nv_bfloat16 *uhi, *ulo, *w1hi, *w1lo, *ghi, *glo, *w2hi, *w2lo;
    cudaGetSymbolAddress((void**)&z1,   g_z1);
    cudaGetSymbolAddress((void**)&ssq,  g_ssq);
    cudaGetSymbolAddress((void**)&s1,   g_s1);
    cudaGetSymbolAddress((void**)&uhi,  g_uhi);
    cudaGetSymbolAddress((void**)&ulo,  g_ulo);
    cudaGetSymbolAddress((void**)&w1hi, g_w1hi);
    cudaGetSymbolAddress((void**)&w1lo, g_w1lo);
    cudaGetSymbolAddress((void**)&ghi,  g_ghi);
    cudaGetSymbolAddress((void**)&glo,  g_glo);
    cudaGetSymbolAddress((void**)&w2hi, g_w2hi);
    cudaGetSymbolAddress((void**)&w2lo, g_w2lo);

    cudaFuncSetAttribute(gemm_hmma_bf16x2,
                         cudaFuncAttributeMaxDynamicSharedMemorySize, GEMM_SMEM);

    // 0) zero row sum-of-squares
    zero_f32<<<(BT + 255) / 256, 256>>>(ssq, BT);

    // 1) split inputs/weights to bf16 hi/lo
    split_bf16<<<((BT * D_ / 4) + 255) / 256, 256>>>(u,     uhi,  ulo,  BT * D_ / 4);
    split_bf16<<<((TWOE * D_ / 4) + 255) / 256, 256>>>(W_in, w1hi, w1lo, TWOE * D_ / 4);
    split_bf16<<<((D_ * E_ / 4) + 255) / 256, 256>>>(W_out, w2hi, w2lo, D_ * E_ / 4);

    // 2) in_proj GEMM (HMMA) + bias -> z1; ssq fused in epilogue
    {
        dim3 grid(TWOE / GN, BT / GM);
        gemm_hmma_bf16x2<<<grid, NTHR, GEMM_SMEM>>>(uhi, ulo, w1hi, w1lo, b_in, z1,
                                                    BT, TWOE, D_, ssq);
    }
    // 3) row scale from fused ssq
    s1_from_ssq<<<(BT + 255) / 256, 256>>>(ssq, s1, BT);

    // 4) conv + gate -> gated bf16 hi/lo
    conv_gate<<<(BT * E_) / 256, 256>>>(z1, s1, innw, conv_w, conv_b, ghi, glo);

    // 5) out_proj GEMM + bias -> out (raw)
    {
        dim3 grid(D_ / GN, BT / GM);
        gemm_hmma_bf16x2<<<grid, NTHR, GEMM_SMEM>>>(ghi, glo, w2hi, w2lo, b_out, out,
                                                    BT, D_, E_, nullptr);
    }
    // 6) in-place RMSNorm on out rows
    out_rmsnorm<<<BT, 256>>>(out, outnw);
}

// round 10
// speedup vs baseline: 1.1102x; 1.1102x over previous
#include <cuda_runtime.h>
#include <cuda_bf16.h>
#include <cstdint>

// ---------------------------------------------------------------------------
// Problem constants
// ---------------------------------------------------------------------------
#define B_   4
#define T_   4096
#define D_   1024
#define E_   1024
#define TWOE 2048
#define BT   (B_ * T_)          // 16384 rows
#define EPS_ 1e-8f

// ---------------------------------------------------------------------------
// Scratch (__device__ globals; no runtime allocation allowed)
// ---------------------------------------------------------------------------
__device__ float         g_z1[(size_t)BT * TWOE];     // in_proj pre-norm (fp32)
__device__ float         g_ssq[BT];                   // row sum-of-squares
__device__ float         g_s1[BT];                    // row rsqrt scale
__device__ __nv_bfloat16 g_uhi[(size_t)BT * D_];
__device__ __nv_bfloat16 g_ulo[(size_t)BT * D_];
__device__ __nv_bfloat16 g_w1hi[(size_t)TWOE * D_];
__device__ __nv_bfloat16 g_w1lo[(size_t)TWOE * D_];
__device__ __nv_bfloat16 g_ghi[(size_t)BT * E_];
__device__ __nv_bfloat16 g_glo[(size_t)BT * E_];
__device__ __nv_bfloat16 g_w2hi[(size_t)D_ * E_];
__device__ __nv_bfloat16 g_w2lo[(size_t)D_ * E_];

// ---------------------------------------------------------------------------
// HMMA split-bf16 GEMM (NT): C[m,n] = sum_k A[m,k]*B[n,k] + bias[n]
//   C = Ahi*Bhi + Alo*Bhi + Ahi*Blo   (fp32 accum; lo*lo dropped)
// 128x128 CTA tile, GK=32 (two k16 steps per barrier), 8 warps (64x32 warp
// tile), 3-stage cp.async circular pipeline (wait_group 1, one barrier per
// chunk), 96KB dynamic smem, 2 CTAs/SM.
// Inner loop: ALL fragment ldmatrix issued up front into DISTINCT registers
// (no B-register reuse -> no WAR hazard), then 48 hazard-free MMAs.
// Swizzle (64B rows): row r, 16B chunk c -> r*64 + ((c ^ ((r>>1)&3)) * 16).
// Optional: epilogue atomically accumulates per-row sum(C^2) into ssq.
// ---------------------------------------------------------------------------
#define GM 128
#define GN 128
#define GK 32
#define ROWB 64                   // bytes per smem row (32 bf16)
#define TILEB (128 * ROWB)        // 8192 B per tile
#define STAGEB (4 * TILEB)        // 32768 B (Ahi, Alo, Bhi, Blo)
#define STAGES 3
#define GEMM_SMEM (STAGES * STAGEB)   // 98304 B

__device__ __forceinline__ uint32_t smem_u32(const void* p) {
    uint32_t a;
    asm("{ .reg .u64 t; cvta.to.shared.u64 t, %1; cvt.u32.u64 %0, t; }" : "=r"(a) : "l"(p));
    return a;
}
__device__ __forceinline__ void cp_async16(uint32_t dst, const void* src) {
    asm volatile("cp.async.cg.shared.global [%0], [%1], 16;\n" :: "r"(dst), "l"(src));
}
__device__ __forceinline__ void cp_commit() { asm volatile("cp.async.commit_group;\n"); }
template <int N>
__device__ __forceinline__ void cp_wait() { asm volatile("cp.async.wait_group %0;\n" :: "n"(N)); }

__device__ __forceinline__ void ldmat_x4(uint32_t* r, uint32_t addr) {
    asm volatile("ldmatrix.sync.aligned.m8n8.x4.shared.b16 {%0,%1,%2,%3}, [%4];"
                 : "=r"(r[0]), "=r"(r[1]), "=r"(r[2]), "=r"(r[3]) : "r"(addr));
}
__device__ __forceinline__ void mma_bf16(float* d, const uint32_t* a, const uint32_t* b) {
    asm volatile(
        "mma.sync.aligned.m16n8k16.row.col.f32.bf16.bf16.f32 "
        "{%0,%1,%2,%3}, {%4,%5,%6,%7}, {%8,%9}, {%0,%1,%2,%3};"
        : "+f"(d[0]), "+f"(d[1]), "+f"(d[2]), "+f"(d[3])
        : "r"(a[0]), "r"(a[1]), "r"(a[2]), "r"(a[3]), "r"(b[0]), "r"(b[1]));
}

// swizzled byte offset within one 128x32 tile for (row, 16B-chunk 0..3)
__device__ __forceinline__ uint32_t swz(int row, int c16) {
    return (uint32_t)(row * ROWB + ((c16 ^ ((row >> 1) & 3)) * 16));
}

__global__ __launch_bounds__(256, 2)
void gemm_hmma_bf16x2(const __nv_bfloat16* __restrict__ Ahi, const __nv_bfloat16* __restrict__ Alo,
                      const __nv_bfloat16* __restrict__ Bhi, const __nv_bfloat16* __restrict__ Blo,
                      const float* __restrict__ bias, float* __restrict__ C,
                      int M, int N, int K, float* __restrict__ ssq)
{
    extern __shared__ char smem[];
    const uint32_t sbase = smem_u32(smem);
    const int tid  = threadIdx.x;
    const int wid  = tid >> 5;
    const int lane = tid & 31;
    const int bm = blockIdx.y * GM;
    const int bn = blockIdx.x * GN;
    const int wm = (wid >> 2) * 64;            // 0 / 64
    const int wn = (wid & 3) * 32;             // 0 / 32 / 64 / 96

    // stage loader: 4 tiles x 128 rows x 4 chunks(16B) = 2048 cp.async / 256 thr
    auto load_stage = [&](int stage, int k0) {
        const uint32_t dst0 = sbase + stage * STAGEB;
        #pragma unroll
        for (int i = 0; i < 8; ++i) {
            int id  = tid + i * 256;           // 0..2047
            int t   = id >> 9;                 // tile 0..3
            int w   = id & 511;
            int row = w >> 2;
            int c   = w & 3;
            const __nv_bfloat16* src;
            if      (t == 0) src = Ahi + (size_t)(bm + row) * K + k0 + c * 8;
            else if (t == 1) src = Alo + (size_t)(bm + row) * K + k0 + c * 8;
            else if (t == 2) src = Bhi + (size_t)(bn + row) * K + k0 + c * 8;
            else             src = Blo + (size_t)(bn + row) * K + k0 + c * 8;
            cp_async16(dst0 + t * TILEB + swz(row, c), src);
        }
        cp_commit();
    };

    float acc[4][4][4];
    #pragma unroll
    for (int i = 0; i < 4; ++i)
        #pragma unroll
        for (int j = 0; j < 4; ++j)
            #pragma unroll
            for (int q = 0; q < 4; ++q) acc[i][j][q] = 0.f;

    const int chunks = K / GK;
    load_stage(0, 0);
    load_stage(1, GK);

    // lane->tile-offset decode for ldmatrix (fixed per lane)
    const int l8  = lane & 7;
    const int sel = lane >> 3;                 // 0..3
    const int a_row = (sel & 1) * 8 + l8;
    const int a_c   = sel >> 1;                // 8-col half within a k16 step
    const int b_row = (sel >> 1) * 8 + l8;
    const int b_c   = sel & 1;

    uint32_t ra[2][4], rb[2][2];
    #pragma unroll
    for (int s = 0; s < 2; ++s) {
        #pragma unroll
        for (int mi = 0; mi < 4; ++mi)
            ra[s][mi] = swz(wm + mi * 16 + a_row, 2 * s + a_c);
        #pragma unroll
        for (int jp = 0; jp < 2; ++jp)
            rb[s][jp] = swz(wn + jp * 16 + b_row, 2 * s + b_c);
    }

    int stage = 0;
    for (int ch = 0; ch < chunks; ++ch) {
        cp_wait<1>();                           // current stage landed
        __syncthreads();                        // visible; oldest buffer consumed
        if (ch + 2 < chunks) {
            int ns = stage + 2; if (ns >= STAGES) ns -= STAGES;
            load_stage(ns, (ch + 2) * GK);
        }

        const uint32_t st = sbase + stage * STAGEB;
        const uint32_t aHiB = st + 0 * TILEB;
        const uint32_t aLoB = st + 1 * TILEB;
        const uint32_t bHiB = st + 2 * TILEB;
        const uint32_t bLoB = st + 3 * TILEB;

        #pragma unroll
        for (int s = 0; s < 2; ++s) {           // two k16 steps, no barrier between
            // --- ALL fragment loads up front, distinct registers ---
            uint32_t ahi[4][4], alo[4][4], bhi[4][2], blo[4][2];
            #pragma unroll
            for (int mi = 0; mi < 4; ++mi) {
                ldmat_x4(ahi[mi], aHiB + ra[s][mi]);
                ldmat_x4(alo[mi], aLoB + ra[s][mi]);
            }
            #pragma unroll
            for (int jp = 0; jp < 2; ++jp) {
                uint32_t th[4], tl[4];
                ldmat_x4(th, bHiB + rb[s][jp]);
                ldmat_x4(tl, bLoB + rb[s][jp]);
                bhi[jp*2  ][0] = th[0]; bhi[jp*2  ][1] = th[1];
                bhi[jp*2+1][0] = th[2]; bhi[jp*2+1][1] = th[3];
                blo[jp*2  ][0] = tl[0]; blo[jp*2  ][1] = tl[1];
                blo[jp*2+1][0] = tl[2]; blo[jp*2+1][1] = tl[3];
            }
            // --- 48 hazard-free MMAs ---
            #pragma unroll
            for (int mi = 0; mi < 4; ++mi)
                #pragma unroll
                for (int nj = 0; nj < 4; ++nj) {
                    mma_bf16(acc[mi][nj], ahi[mi], bhi[nj]);
                    mma_bf16(acc[mi][nj], alo[mi], bhi[nj]);
                    mma_bf16(acc[mi][nj], ahi[mi], blo[nj]);
                }
        }

        ++stage; if (stage >= STAGES) stage = 0;
    }

    // epilogue: frag layout row = lane/4 (+8), col = 2*(lane%4) (+1)
    const int er = lane >> 2;
    const int ec = (lane & 3) * 2;
    #pragma unroll
    for (int mi = 0; mi < 4; ++mi) {
        float pr0 = 0.f, pr1 = 0.f;
        #pragma unroll
        for (int nj = 0; nj < 4; ++nj) {
            int row0 = bm + wm + mi * 16 + er;
            int col  = bn + wn + nj * 8 + ec;
            float b0 = bias[col], b1 = bias[col + 1];
            float v00 = acc[mi][nj][0] + b0, v01 = acc[mi][nj][1] + b1;
            float v10 = acc[mi][nj][2] + b0, v11 = acc[mi][nj][3] + b1;
            *(float2*)&C[(size_t)row0 * N + col]       = make_float2(v00, v01);
            *(float2*)&C[(size_t)(row0 + 8) * N + col] = make_float2(v10, v11);
            pr0 += v00 * v00 + v01 * v01;
            pr1 += v10 * v10 + v11 * v11;
        }
        if (ssq) {
            int row0 = bm + wm + mi * 16 + er;
            #pragma unroll
            for (int o = 1; o < 4; o <<= 1) {
                pr0 += __shfl_xor_sync(0xffffffff, pr0, o);
                pr1 += __shfl_xor_sync(0xffffffff, pr1, o);
            }
            if ((lane & 3) == 0) {
                atomicAdd(&ssq[row0],     pr0);
                atomicAdd(&ssq[row0 + 8], pr1);
            }
        }
    }
}

// ---------------------------------------------------------------------------
// Elementwise kernels
// ---------------------------------------------------------------------------
__global__ void zero_f32(float* __restrict__ p, int n)
{
    int i = blockIdx.x * blockDim.x + threadIdx.x;
    if (i < n) p[i] = 0.f;
}

__global__ void split_bf16(const float* __restrict__ x,
                           __nv_bfloat16* __restrict__ hi, __nv_bfloat16* __restrict__ lo,
                           int n4)
{
    int i = blockIdx.x * blockDim.x + threadIdx.x;
    if (i >= n4) return;
    float4 v = ((const float4*)x)[i];
    __nv_bfloat16 h[4], l[4];
    float f[4] = {v.x, v.y, v.z, v.w};
    #pragma unroll
    for (int j = 0; j < 4; ++j) {
        h[j] = __float2bfloat16(f[j]);
        l[j] = __float2bfloat16(f[j] - __bfloat162float(h[j]));
    }
    ((uint2*)hi)[i] = *(uint2*)h;
    ((uint2*)lo)[i] = *(uint2*)l;
}

__global__ void s1_from_ssq(const float* __restrict__ ssq, float* __restrict__ s, int n)
{
    int i = blockIdx.x * blockDim.x + threadIdx.x;
    if (i < n) s[i] = rsqrtf(ssq[i] * (1.0f / TWOE) + EPS_);
}

__global__ void conv_gate(const float* __restrict__ z1, const float* __restrict__ s1,
                          const float* __restrict__ innw,
                          const float* __restrict__ cw, const float* __restrict__ cb,
                          __nv_bfloat16* __restrict__ ghi, __nv_bfloat16* __restrict__ glo)
{
    const int idx = blockIdx.x * blockDim.x + threadIdx.x;   // over BT*E
    const int e   = idx & (E_ - 1);
    const int row = idx >> 10;
    const int t   = row & (T_ - 1);

    const float wn  = innw[e];
    const float wnv = innw[E_ + e];
    const float w0 = cw[e * 3 + 0], w1 = cw[e * 3 + 1], w2 = cw[e * 3 + 2];

    const float sc = s1[row];
    float xm = cb[e];
    if (t > 0)
        xm = fmaf(w0, z1[(size_t)(row - 1) * TWOE + e] * s1[row - 1] * wn, xm);
    xm = fmaf(w1, z1[(size_t)row * TWOE + e] * sc * wn, xm);
    if (t < T_ - 1)
        xm = fmaf(w2, z1[(size_t)(row + 1) * TWOE + e] * s1[row + 1] * wn, xm);
    const float v = z1[(size_t)row * TWOE + E_ + e] * sc * wnv;
    const float g = v * xm;
    __nv_bfloat16 h = __float2bfloat16(g);
    ghi[idx] = h;
    glo[idx] = __float2bfloat16(g - __bfloat162float(h));
}

__global__ void out_rmsnorm(float* __restrict__ out, const float* __restrict__ w)
{
    const int row = blockIdx.x;
    float4* p = (float4*)(out + (size_t)row * D_);
    float4 v = p[threadIdx.x];                  // 256 x 4 = 1024
    float acc = v.x*v.x + v.y*v.y + v.z*v.z + v.w*v.w;
    #pragma unroll
    for (int o = 16; o > 0; o >>= 1) acc += __shfl_xor_sync(0xffffffff, acc, o);
    __shared__ float warpsum[8];
    __shared__ float s_bcast;
    if ((threadIdx.x & 31) == 0) warpsum[threadIdx.x >> 5] = acc;
    __syncthreads();
    if (threadIdx.x == 0) {
        float tsum = 0.f;
        #pragma unroll
        for (int wi = 0; wi < 8; ++wi) tsum += warpsum[wi];
        s_bcast = rsqrtf(tsum * (1.0f / D_) + EPS_);
    }
    __syncthreads();
    const float s = s_bcast;
    float4 wv = *(const float4*)&w[threadIdx.x * 4];
    v.x *= s * wv.x; v.y *= s * wv.y; v.z *= s * wv.z; v.w *= s * wv.w;
    p[threadIdx.x] = v;
}

// ---------------------------------------------------------------------------
// Launch
// Inputs (metadata order): u, W_in, b_in, in_norm_w, conv_w, conv_b,
//                          W_out, b_out, out_norm_w
// ---------------------------------------------------------------------------
extern "C" void kernel_launch(void* const* d_in, const int* in_sizes, int n_in,
                              void* d_out, int out_size)
{
    const float* u      = (const float*)d_in[0];
    const float* W_in   = (const float*)d_in[1];
    const float* b_in   = (const float*)d_in[2];
    const float* innw   = (const float*)d_in[3];
    const float* conv_w = (const float*)d_in[4];
    const float* conv_b = (const float*)d_in[5];
    const float* W_out  = (const float*)d_in[6];
    const float* b_out  = (const float*)d_in[7];
    const float* outnw  = (const float*)d_in[8];
    float* out = (float*)d_out;

    float *z1, *ssq, *s1;
    __nv_bfloat16 *uhi, *ulo, *w1hi, *w1lo, *ghi, *glo, *w2hi, *w2lo;
    cudaGetSymbolAddress((void**)&z1,   g_z1);
    cudaGetSymbolAddress((void**)&ssq,  g_ssq);
    cudaGetSymbolAddress((void**)&s1,   g_s1);
    cudaGetSymbolAddress((void**)&uhi,  g_uhi);
    cudaGetSymbolAddress((void**)&ulo,  g_ulo);
    cudaGetSymbolAddress((void**)&w1hi, g_w1hi);
    cudaGetSymbolAddress((void**)&w1lo, g_w1lo);
    cudaGetSymbolAddress((void**)&ghi,  g_ghi);
    cudaGetSymbolAddress((void**)&glo,  g_glo);
    cudaGetSymbolAddress((void**)&w2hi, g_w2hi);
    cudaGetSymbolAddress((void**)&w2lo, g_w2lo);

    cudaFuncSetAttribute(gemm_hmma_bf16x2,
                         cudaFuncAttributeMaxDynamicSharedMemorySize, GEMM_SMEM);

    // 0) zero row sum-of-squares
    zero_f32<<<(BT + 255) / 256, 256>>>(ssq, BT);

    // 1) split inputs/weights to bf16 hi/lo
    split_bf16<<<((BT * D_ / 4) + 255) / 256, 256>>>(u,     uhi,  ulo,  BT * D_ / 4);
    split_bf16<<<((TWOE * D_ / 4) + 255) / 256, 256>>>(W_in, w1hi, w1lo, TWOE * D_ / 4);
    split_bf16<<<((D_ * E_ / 4) + 255) / 256, 256>>>(W_out, w2hi, w2lo, D_ * E_ / 4);

    // 2) in_proj GEMM (HMMA) + bias -> z1; ssq fused in epilogue
    {
        dim3 grid(TWOE / GN, BT / GM);
        gemm_hmma_bf16x2<<<grid, 256, GEMM_SMEM>>>(uhi, ulo, w1hi, w1lo, b_in, z1,
                                                   BT, TWOE, D_, ssq);
    }
    // 3) row scale from fused ssq
    s1_from_ssq<<<(BT + 255) / 256, 256>>>(ssq, s1, BT);

    // 4) conv + gate -> gated bf16 hi/lo
    conv_gate<<<(BT * E_) / 256, 256>>>(z1, s1, innw, conv_w, conv_b, ghi, glo);

    // 5) out_proj GEMM + bias -> out (raw)
    {
        dim3 grid(D_ / GN, BT / GM);
        gemm_hmma_bf16x2<<<grid, 256, GEMM_SMEM>>>(ghi, glo, w2hi, w2lo, b_out, out,
                                                   BT, D_, E_, nullptr);
    }
    // 6) in-place RMSNorm on out rows
    out_rmsnorm<<<BT, 256>>>(out, outnw);
}